// round 16
// baseline (speedup 1.0000x reference)
#include <cuda_runtime.h>
#include <cstdint>

#define BB 64
#define TT 1024
#define KK 256
#define HALF 128
#define SROWS 224          // transT rows cached in backtrace SMEM (224 KB)

// ---------------- scratch ---------------------------------------------------
__device__ float g_state[TT * BB * KK];    // all forward states, 64 MB
__device__ float g_transT[KK * KK];        // transposed transitions

// ---------------- helpers ---------------------------------------------------
__device__ __forceinline__ uint32_t smem_u32(const void* p) {
    return (uint32_t)__cvta_generic_to_shared(p);
}

// monotone float->u32 map: preserves ordering exactly (finite values)
__device__ __forceinline__ unsigned fmono(float f) {
    int b = __float_as_int(f);
    return (unsigned)(b ^ ((b >> 31) | 0x80000000));
}

__device__ __forceinline__ void cluster_sync_all() {
    asm volatile("barrier.cluster.arrive.aligned;" ::: "memory");
    asm volatile("barrier.cluster.wait.aligned;" ::: "memory");
}

__device__ __forceinline__ uint32_t mapa_peer(uint32_t laddr, unsigned peer) {
    uint32_t raddr;
    asm volatile("mapa.shared::cluster.u32 %0, %1, %2;"
                 : "=r"(raddr) : "r"(laddr), "r"(peer));
    return raddr;
}

__device__ __forceinline__ void mbar_init(uint32_t addr, unsigned count) {
    asm volatile("mbarrier.init.shared.b64 [%0], %1;" :: "r"(addr), "r"(count) : "memory");
}
// local arrive(1) + expect 'bytes' of incoming async-store traffic this phase
__device__ __forceinline__ void mbar_arrive_expect_tx(uint32_t addr, unsigned bytes) {
    asm volatile("mbarrier.arrive.expect_tx.shared.b64 _, [%0], %1;"
                 :: "r"(addr), "r"(bytes) : "memory");
}
__device__ __forceinline__ void mbar_wait_cluster(uint32_t addr, unsigned parity) {
    asm volatile(
        "{\n\t"
        ".reg .pred P1;\n\t"
        "WAIT_%=:\n\t"
        "mbarrier.try_wait.parity.acquire.cluster.shared::cta.b64 P1, [%0], %1, 0x989680;\n\t"
        "@P1 bra.uni DONE_%=;\n\t"
        "bra.uni WAIT_%=;\n\t"
        "DONE_%=:\n\t"
        "}"
        :: "r"(addr), "r"(parity) : "memory");
}
// one-way async store to cluster SMEM; counts 8 bytes on the given mbarrier
__device__ __forceinline__ void st_async_b64(uint32_t raddr, float2 v, uint32_t rmbar) {
    unsigned long long u;
    memcpy(&u, &v, 8);
    asm volatile(
        "st.async.weak.shared::cluster.mbarrier::complete_tx::bytes.b64 [%0], %1, [%2];"
        :: "r"(raddr), "l"(u), "r"(rmbar) : "memory");
}

// bit-exact add: rn(sv*1.0f + tr) == rn(sv + tr); FFMA-imm form runs at rt 1
__device__ __forceinline__ float addx(float sv, float tr) {
    return __fmaf_rn(sv, 1.0f, tr);
}

__global__ void noop_kernel() {}

// ---------------- transpose kernel ------------------------------------------
__global__ void transpose_kernel(const float* __restrict__ trans)
{
    __shared__ float tile[32][33];
    int bx = blockIdx.x, by = blockIdx.y;
    int x = bx * 32 + threadIdx.x;
    #pragma unroll
    for (int r = 0; r < 4; ++r) {
        int y = by * 32 + threadIdx.y + r * 8;
        tile[threadIdx.y + r * 8][threadIdx.x] = trans[y * KK + x];
    }
    __syncthreads();
    int x2 = by * 32 + threadIdx.x;
    #pragma unroll
    for (int r = 0; r < 4; ++r) {
        int y2 = bx * 32 + threadIdx.y + r * 8;
        g_transT[y2 * KK + x2] = tile[threadIdx.x][threadIdx.y + r * 8];
    }
}

// ---------------- forward kernel (R6 scheme @ 512 threads) ------------------
// 2-CTA cluster per batch. CTA rank owns j in [rank*128,+128).
// 16 warps; warp w owns 8 j columns. lane = g*4 + q (g = i-group 0..7,
// q = j-pair 0..3): thread covers j pair jcol = rank*128 + w*8 + q*2 and
// i = k*8 + g. Trans in registers (64 floats). Peer half exchanged via
// st.async + tx-counting mbarriers (R6-proven); __syncthreads drains nothing
// (st.async is async-proxy). 4 warps/SMSP for latency hiding.
__global__ void __cluster_dims__(2, 1, 1) __launch_bounds__(512, 1)
fwd_kernel(const float* __restrict__ em, const float* __restrict__ trans)
{
    __shared__ float st[2][KK];
    __shared__ __align__(8) unsigned long long mb[2];

    const int bid  = blockIdx.x;
    const int b    = bid >> 1;
    const unsigned rank = bid & 1;
    const unsigned peer = rank ^ 1u;
    const int tid  = threadIdx.x;
    const int w    = tid >> 5;              // 0..15
    const int lane = tid & 31;
    const int q    = lane & 3;
    const int g    = lane >> 2;
    const int jcol = rank * HALF + w * 8 + q * 2;

    const uint32_t mb0_l = smem_u32(&mb[0]);
    const uint32_t mb1_l = mb0_l + 8;
    if (tid == 0) { mbar_init(mb0_l, 1); mbar_init(mb1_l, 1); }

    // transition registers: trA/trB[k] = trans[half*128 + k*8+g][jcol..jcol+1]
    float2 trA[16], trB[16];
    #pragma unroll
    for (int k = 0; k < 16; ++k)
        trA[k] = *(const float2*)&trans[(rank * HALF + k * 8 + g) * KK + jcol];
    #pragma unroll
    for (int k = 0; k < 16; ++k)
        trB[k] = *(const float2*)&trans[(peer * HALF + k * 8 + g) * KK + jcol];

    // initial state = emissions[b,0,:] (both CTAs load full row locally)
    if (tid < KK) {
        float v = em[(b * TT) * KK + tid];
        st[0][tid] = v;
        if (rank == 0) g_state[b * KK + tid] = v;
    }
    __syncthreads();
    cluster_sync_all();          // peer mbar init complete before any st.async

    const bool writer = (lane < 4);
    const int jW = rank * HALF + w * 8 + lane * 2;    // writer's j-pair
    const uint32_t pA0 = mapa_peer(smem_u32(&st[0][jW]), peer);
    const uint32_t pA1 = mapa_peer(smem_u32(&st[1][jW]), peer);
    const uint32_t rmb0 = mapa_peer(mb0_l, peer);
    const uint32_t rmb1 = mapa_peer(mb1_l, peer);
    unsigned p0 = 0, p1 = 0;

    float2 emCur = make_float2(0.f, 0.f);
    if (writer)
        emCur = __ldg((const float2*)&em[((b * TT + 1) * KK) + jW]);

    for (int t = 1; t < TT; ++t) {
        const int nb = t & 1;            // buffer being written (state t)
        const float* cur = st[nb ^ 1];
        float*       nxt = st[nb];

        // announce this phase's expected incoming bytes (local, cheap).
        if (tid == 0)
            mbar_arrive_expect_tx(nb ? mb1_l : mb0_l, 512u);

        // prefetch next step's emission
        float2 emNxt = make_float2(0.f, 0.f);
        if (writer && (t + 1 < TT))
            emNxt = __ldg((const float2*)&em[((b * TT + t + 1) * KK) + jW]);

        // ---- phase A: own-half i, 2-way interleaved chains (exact) ----
        float a0e, a1e, a0o, a1o;
        {
            float s0 = cur[rank * HALF + g];
            float s1 = cur[rank * HALF + 8 + g];
            a0e = addx(s0, trA[0].x); a1e = addx(s0, trA[0].y);
            a0o = addx(s1, trA[1].x); a1o = addx(s1, trA[1].y);
        }
        #pragma unroll
        for (int k = 2; k < 16; k += 2) {
            float s0 = cur[rank * HALF + k * 8 + g];
            float s1 = cur[rank * HALF + (k + 1) * 8 + g];
            a0e = fmaxf(a0e, addx(s0, trA[k].x));
            a1e = fmaxf(a1e, addx(s0, trA[k].y));
            a0o = fmaxf(a0o, addx(s1, trA[k + 1].x));
            a1o = fmaxf(a1o, addx(s1, trA[k + 1].y));
        }

        // ---- wait for peer half of state(t-1): tx-complete mbar ----
        if (t >= 2) {
            if (nb) { mbar_wait_cluster(mb0_l, p0); p0 ^= 1u; }   // cur buf = 0
            else    { mbar_wait_cluster(mb1_l, p1); p1 ^= 1u; }   // cur buf = 1
        }

        // ---- phase B: peer-half i ----
        #pragma unroll
        for (int k = 0; k < 16; k += 2) {
            float s0 = cur[peer * HALF + k * 8 + g];
            float s1 = cur[peer * HALF + (k + 1) * 8 + g];
            a0e = fmaxf(a0e, addx(s0, trB[k].x));
            a1e = fmaxf(a1e, addx(s0, trB[k].y));
            a0o = fmaxf(a0o, addx(s1, trB[k + 1].x));
            a1o = fmaxf(a1o, addx(s1, trB[k + 1].y));
        }
        float a0 = fmaxf(a0e, a0o);
        float a1 = fmaxf(a1e, a1o);

        // butterfly max over the 8 i-groups (lane bits 2..4)
        #pragma unroll
        for (int off = 4; off <= 16; off <<= 1) {
            a0 = fmaxf(a0, __shfl_xor_sync(0xffffffffu, a0, off));
            a1 = fmaxf(a1, __shfl_xor_sync(0xffffffffu, a1, off));
        }

        if (writer) {
            float2 ns = make_float2(a0 + emCur.x, a1 + emCur.y);
            *(float2*)&nxt[jW] = ns;                            // local copy
            st_async_b64(nb ? pA1 : pA0, ns, nb ? rmb1 : rmb0); // peer copy 8B
            *(float2*)&g_state[(t * BB + b) * KK + jW] = ns;    // for backtrace
        }
        emCur = emNxt;

        __syncthreads();   // local visibility of nxt[own half] for next phase A
    }

    // drain: consume the final phase of buffer 1 so no st.async targets our
    // SMEM after exit.
    mbar_wait_cluster(mb1_l, p1);
    cluster_sync_all();
}

// ---------------- backtrace: serial argmax recompute along decoded path -----
// One CTA per batch, one active warp. Chain loop UNROLLED x8 (prefetch in
// registers). Per step: lane-local argmax slot via sel-tree computed
// CONCURRENTLY with redux.max (independent), then one select + redux.min.
// Exact first-index tie-break: a lane's first slot achieving its local max is
// its first slot achieving gmax (when local max == gmax); global min over
// candidates lane*8+slot = first global argmax.
extern __shared__ float sT[];

__global__ void __launch_bounds__(256, 1) backtrace_kernel(float* __restrict__ out)
{
    const int b   = blockIdx.x;
    const int tid = threadIdx.x;

    for (int idx = tid; idx < SROWS * (KK / 4); idx += 256)
        ((float4*)sT)[idx] = ((const float4*)g_transT)[idx];
    __syncthreads();
    if (tid >= 32) return;
    const int lane = tid;
    const int base = lane * 8;
    const unsigned FULL = 0xffffffffu;
    const int BIG = 0x7fffffff;

    int cur;

    // lane-local argmax over 8 keys with first-slot tie-break, then global.
    // (u_hi > u_lo) keeps the LOWER slot on ties at every merge -> first-slot.
    auto argmax8 = [&](unsigned u0, unsigned u1, unsigned u2, unsigned u3,
                       unsigned u4, unsigned u5, unsigned u6, unsigned u7) {
        unsigned m01 = max(u0, u1), m23 = max(u2, u3);
        unsigned m45 = max(u4, u5), m67 = max(u6, u7);
        int s01 = (u1 > u0) ? 1 : 0;
        int s23 = (u3 > u2) ? 3 : 2;
        int s45 = (u5 > u4) ? 5 : 4;
        int s67 = (u7 > u6) ? 7 : 6;
        unsigned m03 = max(m01, m23), m47 = max(m45, m67);
        int s03 = (m23 > m01) ? s23 : s01;
        int s47 = (m67 > m45) ? s67 : s45;
        unsigned um = max(m03, m47);
        int sl = (m47 > m03) ? s47 : s03;
        unsigned gmax = __reduce_max_sync(FULL, um);   // sel-tree overlaps this
        int cand = (um == gmax) ? base + sl : BIG;
        return __reduce_min_sync(FULL, cand);
    };

    // ---- last tag: argmax over state row 1023 ----
    {
        const float4* rp = (const float4*)(g_state + (1023 * BB + b) * KK) + lane * 2;
        float4 sa = __ldg(rp), sb = __ldg(rp + 1);
        cur = argmax8(fmono(sa.x), fmono(sa.y), fmono(sa.z), fmono(sa.w),
                      fmono(sb.x), fmono(sb.y), fmono(sb.z), fmono(sb.w));
        if (lane == 0) out[b * TT + (TT - 1)] = (float)cur;
    }

    // one chain step: state row (t-1) given in (sa, sb); updates cur, writes out
    auto argstep = [&](float4 sa, float4 sb, int t) {
        const float* trow = (cur < SROWS) ? (sT + cur * KK)
                                          : (g_transT + cur * KK);
        float4 t0 = *(const float4*)(trow + base);
        float4 t1 = *(const float4*)(trow + base + 4);
        cur = argmax8(fmono(sa.x + t0.x), fmono(sa.y + t0.y),
                      fmono(sa.z + t0.z), fmono(sa.w + t0.w),
                      fmono(sb.x + t1.x), fmono(sb.y + t1.y),
                      fmono(sb.z + t1.z), fmono(sb.w + t1.w));
        if (lane == 0) out[b * TT + (t - 1)] = (float)cur;
    };

    // depth-8 register prefetch; slot d holds row (1022 - d) = (t-1) at t=1023-d
    float4 pfa[8], pfb[8];
    #pragma unroll
    for (int d = 0; d < 8; ++d) {
        const float4* rp = (const float4*)(g_state + ((1022 - d) * BB + b) * KK) + lane * 2;
        pfa[d] = __ldg(rp);
        pfb[d] = __ldg(rp + 1);
    }

    int t = 1023;
    while (t >= 8) {                 // full blocks: slots are compile-time
        #pragma unroll
        for (int uu = 0; uu < 8; ++uu) {
            float4 sa = pfa[uu], sb = pfb[uu];
            int nrow = t - 9;        // refill slot uu for use 8 iters from now
            if (nrow >= 0) {
                const float4* rp = (const float4*)(g_state + (nrow * BB + b) * KK) + lane * 2;
                pfa[uu] = __ldg(rp);
                pfb[uu] = __ldg(rp + 1);
            }
            argstep(sa, sb, t);
            --t;
        }
    }
    while (t >= 1) {                 // tail (<=7 iters): direct loads, no arrays
        const float4* rp = (const float4*)(g_state + ((t - 1) * BB + b) * KK) + lane * 2;
        float4 sa = __ldg(rp), sb = __ldg(rp + 1);
        argstep(sa, sb, t);
        --t;
    }
}

// ---------------- launch ----------------------------------------------------
extern "C" void kernel_launch(void* const* d_in, const int* in_sizes, int n_in,
                              void* d_out, int out_size)
{
    const float* em    = (const float*)d_in[0];  // [B, T, K] fp32
    const float* trans = (const float*)d_in[1];  // [K, K] fp32
    float* out = (float*)d_out;                  // [B, T] fp32

    const int bt_smem = SROWS * KK * (int)sizeof(float);   // 229376
    cudaFuncSetAttribute(backtrace_kernel,
                         cudaFuncAttributeMaxDynamicSharedMemorySize, bt_smem);

    transpose_kernel<<<dim3(8, 8), dim3(32, 8)>>>(trans);   // launch 1
    noop_kernel<<<1, 32>>>();                               // launch 2
    noop_kernel<<<1, 32>>>();                               // launch 3
    fwd_kernel<<<2 * BB, 512>>>(em, trans);                 // launch 4 <- ncu
    backtrace_kernel<<<BB, 256, bt_smem>>>(out);            // launch 5
}

// round 17
// speedup vs baseline: 1.1352x; 1.1352x over previous
#include <cuda_runtime.h>
#include <cstdint>

#define BB 64
#define TT 1024
#define KK 256
#define HALF 128
#define SROWS 224          // transT rows cached in backtrace SMEM (224 KB)

// ---------------- scratch ---------------------------------------------------
__device__ float g_state[TT * BB * KK];    // all forward states, 64 MB
__device__ float g_transT[KK * KK];        // transposed transitions

// ---------------- helpers ---------------------------------------------------
__device__ __forceinline__ uint32_t smem_u32(const void* p) {
    return (uint32_t)__cvta_generic_to_shared(p);
}

// monotone float->u32 map: preserves ordering exactly (finite values)
__device__ __forceinline__ unsigned fmono(float f) {
    int b = __float_as_int(f);
    return (unsigned)(b ^ ((b >> 31) | 0x80000000));
}

__device__ __forceinline__ void cluster_sync_all() {
    asm volatile("barrier.cluster.arrive.aligned;" ::: "memory");
    asm volatile("barrier.cluster.wait.aligned;" ::: "memory");
}

__device__ __forceinline__ uint32_t mapa_peer(uint32_t laddr, unsigned peer) {
    uint32_t raddr;
    asm volatile("mapa.shared::cluster.u32 %0, %1, %2;"
                 : "=r"(raddr) : "r"(laddr), "r"(peer));
    return raddr;
}

__device__ __forceinline__ void mbar_init(uint32_t addr, unsigned count) {
    asm volatile("mbarrier.init.shared.b64 [%0], %1;" :: "r"(addr), "r"(count) : "memory");
}
// local arrive(1) + expect 'bytes' of incoming async-store traffic this phase
__device__ __forceinline__ void mbar_arrive_expect_tx(uint32_t addr, unsigned bytes) {
    asm volatile("mbarrier.arrive.expect_tx.shared.b64 _, [%0], %1;"
                 :: "r"(addr), "r"(bytes) : "memory");
}
__device__ __forceinline__ void mbar_wait_cluster(uint32_t addr, unsigned parity) {
    asm volatile(
        "{\n\t"
        ".reg .pred P1;\n\t"
        "WAIT_%=:\n\t"
        "mbarrier.try_wait.parity.acquire.cluster.shared::cta.b64 P1, [%0], %1, 0x989680;\n\t"
        "@P1 bra.uni DONE_%=;\n\t"
        "bra.uni WAIT_%=;\n\t"
        "DONE_%=:\n\t"
        "}"
        :: "r"(addr), "r"(parity) : "memory");
}
// one-way async store to peer SMEM; counts 8 bytes on the peer's mbarrier
__device__ __forceinline__ void st_async_b64(uint32_t raddr, float2 v, uint32_t rmbar) {
    unsigned long long u;
    memcpy(&u, &v, 8);
    asm volatile(
        "st.async.weak.shared::cluster.mbarrier::complete_tx::bytes.b64 [%0], %1, [%2];"
        :: "r"(raddr), "l"(u), "r"(rmbar) : "memory");
}

// bit-exact add: rn(sv*1.0f + tr) == rn(sv + tr); FFMA-imm form runs at rt 1
__device__ __forceinline__ float addx(float sv, float tr) {
    return __fmaf_rn(sv, 1.0f, tr);
}

__global__ void noop_kernel() {}

// ---------------- transpose kernel ------------------------------------------
__global__ void transpose_kernel(const float* __restrict__ trans)
{
    __shared__ float tile[32][33];
    int bx = blockIdx.x, by = blockIdx.y;
    int x = bx * 32 + threadIdx.x;
    #pragma unroll
    for (int r = 0; r < 4; ++r) {
        int y = by * 32 + threadIdx.y + r * 8;
        tile[threadIdx.y + r * 8][threadIdx.x] = trans[y * KK + x];
    }
    __syncthreads();
    int x2 = by * 32 + threadIdx.x;
    #pragma unroll
    for (int r = 0; r < 4; ++r) {
        int y2 = bx * 32 + threadIdx.y + r * 8;
        g_transT[y2 * KK + x2] = tile[threadIdx.x][threadIdx.y + r * 8];
    }
}

// ---------------- forward kernel (R6 verbatim: st.async exchange) -----------
// 2-CTA cluster per batch. CTA rank owns j in [rank*128,+128).
// Warp w, lane = g*4 + q; thread covers j-quad jcol = rank*128+w*16+q*4 and
// i = k*8 + g. Trans in registers. Peer half exchanged via st.async with
// transaction-counting mbarriers: NO release fence, NO store drain at BAR.
// 256 threads (2 warps/SMSP) — measured local optimum across R4/R16 variants.
__global__ void __cluster_dims__(2, 1, 1) __launch_bounds__(256, 1)
fwd_kernel(const float* __restrict__ em, const float* __restrict__ trans)
{
    __shared__ float st[2][KK];
    __shared__ __align__(8) unsigned long long mb[2];

    const int bid  = blockIdx.x;
    const int b    = bid >> 1;
    const unsigned rank = bid & 1;
    const unsigned peer = rank ^ 1u;
    const int tid  = threadIdx.x;
    const int w    = tid >> 5;
    const int lane = tid & 31;
    const int q    = lane & 3;
    const int g    = lane >> 2;
    const int jcol = rank * HALF + w * 16 + q * 4;

    const uint32_t mb0_l = smem_u32(&mb[0]);
    const uint32_t mb1_l = mb0_l + 8;
    if (tid == 0) { mbar_init(mb0_l, 1); mbar_init(mb1_l, 1); }

    // transition registers
    float4 trA[16], trB[16];
    #pragma unroll
    for (int k = 0; k < 16; ++k)
        trA[k] = *(const float4*)&trans[(rank * HALF + k * 8 + g) * KK + jcol];
    #pragma unroll
    for (int k = 0; k < 16; ++k)
        trB[k] = *(const float4*)&trans[(peer * HALF + k * 8 + g) * KK + jcol];

    // initial state = emissions[b,0,:] (both CTAs load full row locally)
    {
        float v = em[(b * TT) * KK + tid];
        st[0][tid] = v;
        if (rank == 0) g_state[b * KK + tid] = v;
    }
    __syncthreads();
    cluster_sync_all();          // peer mbar init complete before any st.async

    const bool writer = (lane < 4);
    const int jW = rank * HALF + w * 16 + lane * 4;   // writer's j-quad
    const uint32_t pA0 = mapa_peer(smem_u32(&st[0][jW]), peer);
    const uint32_t pA1 = mapa_peer(smem_u32(&st[1][jW]), peer);
    const uint32_t rmb0 = mapa_peer(mb0_l, peer);
    const uint32_t rmb1 = mapa_peer(mb1_l, peer);
    unsigned p0 = 0, p1 = 0;

    float4 emCur = make_float4(0.f, 0.f, 0.f, 0.f);
    if (writer)
        emCur = __ldg((const float4*)&em[((b * TT + 1) * KK) + jW]);

    for (int t = 1; t < TT; ++t) {
        const int nb = t & 1;            // buffer being written (state t)
        const float* cur = st[nb ^ 1];
        float*       nxt = st[nb];

        // announce this phase's expected incoming bytes (local, cheap).
        if (tid == 0)
            mbar_arrive_expect_tx(nb ? mb1_l : mb0_l, 512u);

        // prefetch next step's emission
        float4 emNxt = make_float4(0.f, 0.f, 0.f, 0.f);
        if (writer && (t + 1 < TT))
            emNxt = __ldg((const float4*)&em[((b * TT + t + 1) * KK) + jW]);

        // ---- phase A: own-half i (locally produced, no wait) ----
        float a0, a1, a2, a3;
        {
            float sv = cur[rank * HALF + g];
            a0 = addx(sv, trA[0].x); a1 = addx(sv, trA[0].y);
            a2 = addx(sv, trA[0].z); a3 = addx(sv, trA[0].w);
        }
        #pragma unroll
        for (int k = 1; k < 16; ++k) {
            float sv = cur[rank * HALF + k * 8 + g];
            a0 = fmaxf(a0, addx(sv, trA[k].x));
            a1 = fmaxf(a1, addx(sv, trA[k].y));
            a2 = fmaxf(a2, addx(sv, trA[k].z));
            a3 = fmaxf(a3, addx(sv, trA[k].w));
        }

        // ---- wait for peer half of state(t-1): tx-complete mbar ----
        if (t >= 2) {
            if (nb) { mbar_wait_cluster(mb0_l, p0); p0 ^= 1u; }   // cur buf = 0
            else    { mbar_wait_cluster(mb1_l, p1); p1 ^= 1u; }   // cur buf = 1
        }

        // ---- phase B: peer-half i ----
        #pragma unroll
        for (int k = 0; k < 16; ++k) {
            float sv = cur[peer * HALF + k * 8 + g];
            a0 = fmaxf(a0, addx(sv, trB[k].x));
            a1 = fmaxf(a1, addx(sv, trB[k].y));
            a2 = fmaxf(a2, addx(sv, trB[k].z));
            a3 = fmaxf(a3, addx(sv, trB[k].w));
        }

        // butterfly max over the 8 i-groups (lane bits 2..4)
        #pragma unroll
        for (int off = 4; off <= 16; off <<= 1) {
            a0 = fmaxf(a0, __shfl_xor_sync(0xffffffffu, a0, off));
            a1 = fmaxf(a1, __shfl_xor_sync(0xffffffffu, a1, off));
            a2 = fmaxf(a2, __shfl_xor_sync(0xffffffffu, a2, off));
            a3 = fmaxf(a3, __shfl_xor_sync(0xffffffffu, a3, off));
        }

        if (writer) {
            float4 ns = make_float4(a0 + emCur.x, a1 + emCur.y,
                                    a2 + emCur.z, a3 + emCur.w);
            *(float4*)&nxt[jW] = ns;                            // local copy
            uint32_t pD = nb ? pA1 : pA0;                       // peer copy
            uint32_t pM = nb ? rmb1 : rmb0;
            st_async_b64(pD,     make_float2(ns.x, ns.y), pM);  // 8B tx each
            st_async_b64(pD + 8, make_float2(ns.z, ns.w), pM);
            *(float4*)&g_state[(t * BB + b) * KK + jW] = ns;    // for backtrace
        }
        emCur = emNxt;

        __syncthreads();   // local visibility of nxt[own half] for next phase A
    }

    // drain: consume the final phase of buffer 1 so no st.async targets our
    // SMEM after exit.
    mbar_wait_cluster(mb1_l, p1);
    cluster_sync_all();
}

// ---------------- backtrace: serial argmax recompute along decoded path -----
// One CTA per batch, one active warp. Chain loop UNROLLED x8 (prefetch in
// registers). Per step: lane-local argmax slot via sel-tree computed
// CONCURRENTLY with redux.max (independent), then one select + redux.min.
// Exact first-index tie-break: a lane's first slot achieving its local max is
// its first slot achieving gmax (when local max == gmax); global min over
// candidates lane*8+slot = first global argmax.
extern __shared__ float sT[];

__global__ void __launch_bounds__(256, 1) backtrace_kernel(float* __restrict__ out)
{
    const int b   = blockIdx.x;
    const int tid = threadIdx.x;

    for (int idx = tid; idx < SROWS * (KK / 4); idx += 256)
        ((float4*)sT)[idx] = ((const float4*)g_transT)[idx];
    __syncthreads();
    if (tid >= 32) return;
    const int lane = tid;
    const int base = lane * 8;
    const unsigned FULL = 0xffffffffu;
    const int BIG = 0x7fffffff;

    int cur;

    // lane-local argmax over 8 keys with first-slot tie-break, then global.
    // (u_hi > u_lo) keeps the LOWER slot on ties at every merge -> first-slot.
    auto argmax8 = [&](unsigned u0, unsigned u1, unsigned u2, unsigned u3,
                       unsigned u4, unsigned u5, unsigned u6, unsigned u7) {
        unsigned m01 = max(u0, u1), m23 = max(u2, u3);
        unsigned m45 = max(u4, u5), m67 = max(u6, u7);
        int s01 = (u1 > u0) ? 1 : 0;
        int s23 = (u3 > u2) ? 3 : 2;
        int s45 = (u5 > u4) ? 5 : 4;
        int s67 = (u7 > u6) ? 7 : 6;
        unsigned m03 = max(m01, m23), m47 = max(m45, m67);
        int s03 = (m23 > m01) ? s23 : s01;
        int s47 = (m67 > m45) ? s67 : s45;
        unsigned um = max(m03, m47);
        int sl = (m47 > m03) ? s47 : s03;
        unsigned gmax = __reduce_max_sync(FULL, um);   // sel-tree overlaps this
        int cand = (um == gmax) ? base + sl : BIG;
        return __reduce_min_sync(FULL, cand);
    };

    // ---- last tag: argmax over state row 1023 ----
    {
        const float4* rp = (const float4*)(g_state + (1023 * BB + b) * KK) + lane * 2;
        float4 sa = __ldg(rp), sb = __ldg(rp + 1);
        cur = argmax8(fmono(sa.x), fmono(sa.y), fmono(sa.z), fmono(sa.w),
                      fmono(sb.x), fmono(sb.y), fmono(sb.z), fmono(sb.w));
        if (lane == 0) out[b * TT + (TT - 1)] = (float)cur;
    }

    // one chain step: state row (t-1) given in (sa, sb); updates cur, writes out
    auto argstep = [&](float4 sa, float4 sb, int t) {
        const float* trow = (cur < SROWS) ? (sT + cur * KK)
                                          : (g_transT + cur * KK);
        float4 t0 = *(const float4*)(trow + base);
        float4 t1 = *(const float4*)(trow + base + 4);
        cur = argmax8(fmono(sa.x + t0.x), fmono(sa.y + t0.y),
                      fmono(sa.z + t0.z), fmono(sa.w + t0.w),
                      fmono(sb.x + t1.x), fmono(sb.y + t1.y),
                      fmono(sb.z + t1.z), fmono(sb.w + t1.w));
        if (lane == 0) out[b * TT + (t - 1)] = (float)cur;
    };

    // depth-8 register prefetch; slot d holds row (1022 - d) = (t-1) at t=1023-d
    float4 pfa[8], pfb[8];
    #pragma unroll
    for (int d = 0; d < 8; ++d) {
        const float4* rp = (const float4*)(g_state + ((1022 - d) * BB + b) * KK) + lane * 2;
        pfa[d] = __ldg(rp);
        pfb[d] = __ldg(rp + 1);
    }

    int t = 1023;
    while (t >= 8) {                 // full blocks: slots are compile-time
        #pragma unroll
        for (int uu = 0; uu < 8; ++uu) {
            float4 sa = pfa[uu], sb = pfb[uu];
            int nrow = t - 9;        // refill slot uu for use 8 iters from now
            if (nrow >= 0) {
                const float4* rp = (const float4*)(g_state + (nrow * BB + b) * KK) + lane * 2;
                pfa[uu] = __ldg(rp);
                pfb[uu] = __ldg(rp + 1);
            }
            argstep(sa, sb, t);
            --t;
        }
    }
    while (t >= 1) {                 // tail (<=7 iters): direct loads, no arrays
        const float4* rp = (const float4*)(g_state + ((t - 1) * BB + b) * KK) + lane * 2;
        float4 sa = __ldg(rp), sb = __ldg(rp + 1);
        argstep(sa, sb, t);
        --t;
    }
}

// ---------------- launch ----------------------------------------------------
extern "C" void kernel_launch(void* const* d_in, const int* in_sizes, int n_in,
                              void* d_out, int out_size)
{
    const float* em    = (const float*)d_in[0];  // [B, T, K] fp32
    const float* trans = (const float*)d_in[1];  // [K, K] fp32
    float* out = (float*)d_out;                  // [B, T] fp32

    const int bt_smem = SROWS * KK * (int)sizeof(float);   // 229376
    cudaFuncSetAttribute(backtrace_kernel,
                         cudaFuncAttributeMaxDynamicSharedMemorySize, bt_smem);

    transpose_kernel<<<dim3(8, 8), dim3(32, 8)>>>(trans);   // launch 1
    noop_kernel<<<1, 32>>>();                               // launch 2
    fwd_kernel<<<2 * BB, 256>>>(em, trans);                 // launch 3
    backtrace_kernel<<<BB, 256, bt_smem>>>(out);            // launch 4 <- ncu
}